// round 3
// baseline (speedup 1.0000x reference)
#include <cuda_runtime.h>
#include <cuda_fp16.h>

#define EPSF 1e-6f
#define EXPERTS 64
#define S_MAX 524288
#define SINK_ITERS 10

#define NB_IT 2048
#define NT_IT 256
#define NB_ROW 4096
#define NT_ROW 256

// Scratch (static device allocations; no cudaMalloc allowed)
__device__ __half2 g_e[(size_t)S_MAX * (EXPERTS / 2)];    // exp(logits - rowmax), fp16, 64MB
__device__ float   g_r[S_MAX];                             // row scale
__device__ __align__(16) float g_c[EXPERTS];               // col scale
__device__ float   g_bpart[EXPERTS * NB_IT];               // per-block column partials

// ---------------------------------------------------------------------------
// K1: prep — compute E = exp(x - rowmax) in fp16, init r = 1, c = 1
// One warp per row; lane handles 2 columns (float2 load = 256B/row coalesced).
// ---------------------------------------------------------------------------
__global__ void k_prep(const float* __restrict__ logits, int S) {
    int lane = threadIdx.x & 31;
    int warp = (blockIdx.x * blockDim.x + threadIdx.x) >> 5;
    int nw   = (gridDim.x * blockDim.x) >> 5;

    if (blockIdx.x == 0 && threadIdx.x < EXPERTS) g_c[threadIdx.x] = 1.0f;

    for (int row = warp; row < S; row += nw) {
        float2 x = ((const float2*)logits)[(size_t)row * 32 + lane];
        float m = fmaxf(x.x, x.y);
        #pragma unroll
        for (int o = 16; o; o >>= 1) m = fmaxf(m, __shfl_xor_sync(0xFFFFFFFFu, m, o));
        float e0 = __expf(x.x - m);
        float e1 = __expf(x.y - m);
        g_e[(size_t)row * 32 + lane] = __floats2half2_rn(e0, e1);
        if (lane == 0) g_r[row] = 1.0f;
    }
}

// ---------------------------------------------------------------------------
// K2: one Sinkhorn iteration (row update fused with column partial sums)
// a_i = E_i . c ; r_i <- r_i/(r_i a_i + eps) ; b_j += E_ij * r_i_new
// Deterministic: per-block partials written to g_bpart, no float atomics.
// ---------------------------------------------------------------------------
__global__ void k_iter(int S) {
    int lane = threadIdx.x & 31;
    int wid  = threadIdx.x >> 5;                // warp within block (8 warps)
    int warp = (blockIdx.x * blockDim.x + threadIdx.x) >> 5;
    int nw   = (gridDim.x * blockDim.x) >> 5;

    float2 cc = ((const float2*)g_c)[lane];     // c[2*lane], c[2*lane+1]
    float b0 = 0.f, b1 = 0.f;

    for (int row = warp; row < S; row += nw) {
        float2 ef = __half22float2(g_e[(size_t)row * 32 + lane]);
        float a = ef.x * cc.x + ef.y * cc.y;
        #pragma unroll
        for (int o = 16; o; o >>= 1) a += __shfl_xor_sync(0xFFFFFFFFu, a, o);
        float ri = g_r[row];
        float rn = __fdividef(ri, ri * a + EPSF);
        if (lane == 0) g_r[row] = rn;
        b0 += ef.x * rn;
        b1 += ef.y * rn;
    }

    __shared__ float sb[NT_IT / 32][EXPERTS];
    sb[wid][2 * lane]     = b0;
    sb[wid][2 * lane + 1] = b1;
    __syncthreads();
    if (threadIdx.x < EXPERTS) {
        float s = 0.f;
        #pragma unroll
        for (int w = 0; w < NT_IT / 32; w++) s += sb[w][threadIdx.x];
        g_bpart[threadIdx.x * NB_IT + blockIdx.x] = s;  // [col][block] layout
    }
}

// ---------------------------------------------------------------------------
// K3: reduce column partials, update c_j = c_j * col_target / (c_j*b_j + eps)
// One block per column; fixed-order tree reduction (deterministic).
// ---------------------------------------------------------------------------
__global__ void k_col(float col_target) {
    int j = blockIdx.x;
    float s = 0.f;
    for (int t = threadIdx.x; t < NB_IT; t += blockDim.x)
        s += g_bpart[j * NB_IT + t];
    __shared__ float red[256];
    red[threadIdx.x] = s;
    __syncthreads();
    #pragma unroll
    for (int o = 128; o; o >>= 1) {
        if (threadIdx.x < o) red[threadIdx.x] += red[threadIdx.x + o];
        __syncthreads();
    }
    if (threadIdx.x == 0) {
        float c = g_c[j];
        g_c[j] = c * col_target / (c * red[0] + EPSF);
    }
}

// ---------------------------------------------------------------------------
// K4: final — recompute E in fp32 from logits (accurate ranking path),
// final row normalization (with eps via r_i), top-k + weight normalization.
// Output (float32): [idx block (S*k)] then [weights block (S*k)].
// All writes bounds-guarded against out_n (in float32 elements).
// ---------------------------------------------------------------------------
__global__ void k_final(const float* __restrict__ logits,
                        const int* __restrict__ topk_p, int k_fallback,
                        float* __restrict__ out, int S, size_t out_n) {
    int lane = threadIdx.x & 31;
    int warp = (blockIdx.x * blockDim.x + threadIdx.x) >> 5;
    int nw   = (gridDim.x * blockDim.x) >> 5;

    int k = k_fallback;
    if (topk_p) k = topk_p[0];          // int32 or LE-int64 "2" both read as 2
    if (k < 1) k = 1;
    if (k > 8) k = 8;

    float2 cc = ((const float2*)g_c)[lane];

    for (int row = warp; row < S; row += nw) {
        float2 x = ((const float2*)logits)[(size_t)row * 32 + lane];
        float m = fmaxf(x.x, x.y);
        #pragma unroll
        for (int o = 16; o; o >>= 1) m = fmaxf(m, __shfl_xor_sync(0xFFFFFFFFu, m, o));

        float u0 = expf(x.x - m) * cc.x;   // q_ij / r_i  (ranking invariant in r_i)
        float u1 = expf(x.y - m) * cc.y;

        float A = u0 + u1;
        #pragma unroll
        for (int o = 16; o; o >>= 1) A += __shfl_xor_sync(0xFFFFFFFFu, A, o);

        float ri    = g_r[row];
        float denom = ri * A + EPSF;       // = rowsum(q) + eps

        float lu0 = u0, lu1 = u1;
        float vals[8];
        int   idxs[8];
        for (int t = 0; t < k; t++) {
            float lv; int li;
            if (lu0 >= lu1) { lv = lu0; li = 2 * lane; }       // tie -> lower idx
            else            { lv = lu1; li = 2 * lane + 1; }
            #pragma unroll
            for (int o = 16; o; o >>= 1) {
                float ov = __shfl_xor_sync(0xFFFFFFFFu, lv, o);
                int   oi = __shfl_xor_sync(0xFFFFFFFFu, li, o);
                if (ov > lv || (ov == lv && oi < li)) { lv = ov; li = oi; }
            }
            vals[t] = lv; idxs[t] = li;
            if (li == 2 * lane)     lu0 = -1.f;   // exclude winner
            if (li == 2 * lane + 1) lu1 = -1.f;
        }

        if (lane == 0) {
            float v[8];
            float vs = 0.f;
            for (int t = 0; t < k; t++) {
                v[t] = ri * vals[t] / denom;      // top-k values of normalized q
                vs += v[t];
            }
            float inv = 1.0f / (vs + EPSF);
            for (int t = 0; t < k; t++) {
                size_t pi = (size_t)row * k + t;                      // idx slot
                size_t pw = (size_t)S * k + pi;                       // weight slot
                if (pi < out_n) out[pi] = (float)idxs[t];
                if (pw < out_n) out[pw] = v[t] * inv;
            }
        }
    }
}

// ---------------------------------------------------------------------------
extern "C" void kernel_launch(void* const* d_in, const int* in_sizes, int n_in,
                              void* d_out, int out_size) {
    const float* logits = (const float*)d_in[0];
    float*       out    = (float*)d_out;

    int S = in_sizes[0] / EXPERTS;
    if (S > S_MAX) S = S_MAX;
    if (S < 1) S = 1;
    float col_target = (float)S / (float)EXPERTS;

    // k: read on-device from d_in[1] when present; fallback derived from
    // output size assuming [idx S*k][w S*k] concat layout.
    const int* topk = (n_in > 1) ? (const int*)d_in[1] : nullptr;
    int k_fb = (int)((size_t)out_size / (2 * (size_t)S));
    if (k_fb < 1) k_fb = 1;
    if (k_fb > 8) k_fb = 8;

    k_prep<<<NB_ROW, NT_ROW>>>(logits, S);
    for (int it = 0; it < SINK_ITERS; it++) {
        k_iter<<<NB_IT, NT_IT>>>(S);
        k_col<<<EXPERTS, 256>>>(col_target);
    }
    k_final<<<NB_ROW, NT_ROW>>>(logits, topk, k_fb, out, S, (size_t)out_size);
}

// round 4
// speedup vs baseline: 1.0805x; 1.0805x over previous
#include <cuda_runtime.h>
#include <cuda_fp16.h>

#define EPSF 1e-6f
#define EXPERTS 64
#define S_MAX 524288
#define NB 512
#define NT 256

// Scratch (static device allocations)
__device__ __half2 g_e[(size_t)S_MAX * 32];      // exp(logits - rowmax) fp16, 64MB (128B/row)
__device__ float   g_r[S_MAX];                   // row scale
__device__ __align__(16) float g_c[EXPERTS];     // col scale
__device__ float   g_bpart[EXPERTS * NB];        // per-block column partials
__device__ unsigned g_tick;                      // last-block ticket (zero-init, self-resetting)

__device__ __forceinline__ float2 h2f(unsigned u) {
    __half2 h = *reinterpret_cast<__half2*>(&u);
    return __half22float2(h);
}
__device__ __forceinline__ unsigned f2h2(float a, float b) {
    __half2 h = __floats2half2_rn(a, b);
    return *reinterpret_cast<unsigned*>(&h);
}

// Fold b[64] across the warp. Afterwards b[0], b[1] hold the warp-total for
// columns 2*lane and 2*lane+1. 62 shuffles total (vs 320 for naive).
#define FOLD_STEP(o, h)                                                        \
    {                                                                          \
        bool hi_ = (lane & (o)) != 0;                                          \
        _Pragma("unroll")                                                      \
        for (int i_ = 0; i_ < (h); i_++) {                                     \
            float keep = hi_ ? b[i_ + (h)] : b[i_];                            \
            float send = hi_ ? b[i_] : b[i_ + (h)];                            \
            float got  = __shfl_xor_sync(0xFFFFFFFFu, send, (o));              \
            b[i_] = keep + got;                                                \
        }                                                                      \
    }

// Common kernel tail: block-combine column partials, write g_bpart, and the
// last block to finish reduces all partials and updates g_c (fixed order =
// deterministic). first=true uses c_old = 1 (the prep/iter-1 case).
__device__ __forceinline__ void tail_update(float b0, float b1,
                                            float col_target, bool first) {
    __shared__ float sb[NT / 32][EXPERTS];
    __shared__ float sq[4][EXPERTS];
    __shared__ int   slast;
    int tid = threadIdx.x, lane = tid & 31, wid = tid >> 5;

    sb[wid][2 * lane]     = b0;
    sb[wid][2 * lane + 1] = b1;
    __syncthreads();
    if (tid < EXPERTS) {
        float s = 0.f;
        #pragma unroll
        for (int w = 0; w < NT / 32; w++) s += sb[w][tid];
        g_bpart[tid * NB + blockIdx.x] = s;
    }
    __threadfence();
    if (tid == 0) {
        unsigned t = atomicAdd(&g_tick, 1u);
        slast = (t == NB - 1) ? 1 : 0;
    }
    __syncthreads();
    if (!slast) return;

    // Last block: reduce all NB partials per column (4 threads per column).
    int col = tid & 63, q = tid >> 6;
    float s = 0.f;
    for (int p = q * (NB / 4); p < (q + 1) * (NB / 4); p++)
        s += g_bpart[col * NB + p];
    sq[q][col] = s;
    __syncthreads();
    if (tid < EXPERTS) {
        float btot = sq[0][tid] + sq[1][tid] + sq[2][tid] + sq[3][tid];
        float c = first ? 1.0f : g_c[tid];
        g_c[tid] = c * col_target / (c * btot + EPSF);
    }
    if (tid == 0) g_tick = 0;   // self-reset for next kernel / graph replay
}

// ---------------------------------------------------------------------------
// K1: prep + Sinkhorn iteration 1 fused.
// E = exp(x - rowmax) stored fp16; with r=c=1: a = rowsum, r1 = 1/(a+eps),
// b_j = sum_i E_ij r1_i; tail computes c1 = ct/(b+eps).
// Thread-per-row, no shuffles in the main loop.
// ---------------------------------------------------------------------------
__global__ __launch_bounds__(NT) void k_prep(const float* __restrict__ logits,
                                             int S, float col_target) {
    int tid = threadIdx.x, lane = tid & 31;
    float b[EXPERTS];
    #pragma unroll
    for (int j = 0; j < EXPERTS; j++) b[j] = 0.f;

    for (int row = blockIdx.x * NT + tid; row < S; row += NB * NT) {
        const float4* xp = reinterpret_cast<const float4*>(logits) + (size_t)row * 16;
        float mx = -3.4e38f;
        #pragma unroll
        for (int m = 0; m < 16; m++) {
            float4 v = xp[m];
            mx = fmaxf(mx, fmaxf(fmaxf(v.x, v.y), fmaxf(v.z, v.w)));
        }
        uint4 e[8];
        float a0 = 0.f, a1 = 0.f, a2 = 0.f, a3 = 0.f;
        #pragma unroll
        for (int m = 0; m < 8; m++) {
            float4 v0 = xp[2 * m], v1 = xp[2 * m + 1];   // L1 hits (reload)
            float f0 = __expf(v0.x - mx), f1 = __expf(v0.y - mx);
            float f2 = __expf(v0.z - mx), f3 = __expf(v0.w - mx);
            float f4 = __expf(v1.x - mx), f5 = __expf(v1.y - mx);
            float f6 = __expf(v1.z - mx), f7 = __expf(v1.w - mx);
            e[m].x = f2h2(f0, f1); e[m].y = f2h2(f2, f3);
            e[m].z = f2h2(f4, f5); e[m].w = f2h2(f6, f7);
            a0 += f0 + f4; a1 += f1 + f5; a2 += f2 + f6; a3 += f3 + f7;
        }
        uint4* dp = reinterpret_cast<uint4*>(g_e) + (size_t)row * 8;
        #pragma unroll
        for (int m = 0; m < 8; m++) dp[m] = e[m];

        float a  = (a0 + a1) + (a2 + a3);
        float rn = __fdividef(1.0f, a + EPSF);
        g_r[row] = rn;

        // b from the packed halves (consistent with what iterations will read)
        #pragma unroll
        for (int m = 0; m < 8; m++) {
            float2 f0 = h2f(e[m].x), f1 = h2f(e[m].y);
            float2 f2 = h2f(e[m].z), f3 = h2f(e[m].w);
            b[m*8+0] = fmaf(f0.x, rn, b[m*8+0]); b[m*8+1] = fmaf(f0.y, rn, b[m*8+1]);
            b[m*8+2] = fmaf(f1.x, rn, b[m*8+2]); b[m*8+3] = fmaf(f1.y, rn, b[m*8+3]);
            b[m*8+4] = fmaf(f2.x, rn, b[m*8+4]); b[m*8+5] = fmaf(f2.y, rn, b[m*8+5]);
            b[m*8+6] = fmaf(f3.x, rn, b[m*8+6]); b[m*8+7] = fmaf(f3.y, rn, b[m*8+7]);
        }
    }
    FOLD_STEP(16, 32) FOLD_STEP(8, 16) FOLD_STEP(4, 8) FOLD_STEP(2, 4) FOLD_STEP(1, 2)
    tail_update(b[0], b[1], col_target, true);
}

// ---------------------------------------------------------------------------
// K2: one Sinkhorn iteration, thread-per-row.
// a_i = E_i.c ; r <- r/(r a+eps) ; b_j += E_ij r_new ; tail updates c.
// ---------------------------------------------------------------------------
__global__ __launch_bounds__(NT) void k_iter(int S, float col_target) {
    __shared__ __align__(16) float sc[EXPERTS];
    int tid = threadIdx.x, lane = tid & 31;
    if (tid < EXPERTS) sc[tid] = g_c[tid];
    __syncthreads();

    float b[EXPERTS];
    #pragma unroll
    for (int j = 0; j < EXPERTS; j++) b[j] = 0.f;

    for (int row = blockIdx.x * NT + tid; row < S; row += NB * NT) {
        const uint4* ep = reinterpret_cast<const uint4*>(g_e) + (size_t)row * 8;
        uint4 e[8];
        #pragma unroll
        for (int m = 0; m < 8; m++) e[m] = ep[m];

        float a0 = 0.f, a1 = 0.f, a2 = 0.f, a3 = 0.f;
        #pragma unroll
        for (int m = 0; m < 8; m++) {
            float4 cA = *reinterpret_cast<const float4*>(&sc[m * 8]);
            float4 cB = *reinterpret_cast<const float4*>(&sc[m * 8 + 4]);
            float2 f0 = h2f(e[m].x), f1 = h2f(e[m].y);
            float2 f2 = h2f(e[m].z), f3 = h2f(e[m].w);
            a0 = fmaf(f0.x, cA.x, a0); a1 = fmaf(f0.y, cA.y, a1);
            a2 = fmaf(f1.x, cA.z, a2); a3 = fmaf(f1.y, cA.w, a3);
            a0 = fmaf(f2.x, cB.x, a0); a1 = fmaf(f2.y, cB.y, a1);
            a2 = fmaf(f3.x, cB.z, a2); a3 = fmaf(f3.y, cB.w, a3);
        }
        float a  = (a0 + a1) + (a2 + a3);
        float ri = g_r[row];
        float rn = __fdividef(ri, fmaf(ri, a, EPSF));
        g_r[row] = rn;

        #pragma unroll
        for (int m = 0; m < 8; m++) {
            float2 f0 = h2f(e[m].x), f1 = h2f(e[m].y);
            float2 f2 = h2f(e[m].z), f3 = h2f(e[m].w);
            b[m*8+0] = fmaf(f0.x, rn, b[m*8+0]); b[m*8+1] = fmaf(f0.y, rn, b[m*8+1]);
            b[m*8+2] = fmaf(f1.x, rn, b[m*8+2]); b[m*8+3] = fmaf(f1.y, rn, b[m*8+3]);
            b[m*8+4] = fmaf(f2.x, rn, b[m*8+4]); b[m*8+5] = fmaf(f2.y, rn, b[m*8+5]);
            b[m*8+6] = fmaf(f3.x, rn, b[m*8+6]); b[m*8+7] = fmaf(f3.y, rn, b[m*8+7]);
        }
    }
    FOLD_STEP(16, 32) FOLD_STEP(8, 16) FOLD_STEP(4, 8) FOLD_STEP(2, 4) FOLD_STEP(1, 2)
    tail_update(b[0], b[1], col_target, false);
}

// ---------------------------------------------------------------------------
// K3: final row normalization + top-2 + weight renorm (fast path, k == 2).
// Thread-per-row, fp32 ranking path from original logits, no shuffles.
// Output float32: [idx (S*2)] then [weights (S*2)], written as float2.
// ---------------------------------------------------------------------------
__global__ __launch_bounds__(NT) void k_final2(const float* __restrict__ logits,
                                               float* __restrict__ out, int S) {
    __shared__ __align__(16) float sc[EXPERTS];
    int tid = threadIdx.x;
    if (tid < EXPERTS) sc[tid] = g_c[tid];
    __syncthreads();

    for (int row = blockIdx.x * NT + tid; row < S; row += NB * NT) {
        const float4* xp = reinterpret_cast<const float4*>(logits) + (size_t)row * 16;
        float mx = -3.4e38f;
        #pragma unroll
        for (int m = 0; m < 16; m++) {
            float4 v = xp[m];
            mx = fmaxf(mx, fmaxf(fmaxf(v.x, v.y), fmaxf(v.z, v.w)));
        }
        float A0 = 0.f, A1 = 0.f, A2 = 0.f, A3 = 0.f;
        float m1 = -1.f, m2 = -1.f, i1 = 0.f, i2 = 0.f;
        #pragma unroll
        for (int m = 0; m < 8; m++) {
            float4 v0 = xp[2 * m], v1 = xp[2 * m + 1];
            float u[8];
            u[0] = __expf(v0.x - mx) * sc[m*8+0];
            u[1] = __expf(v0.y - mx) * sc[m*8+1];
            u[2] = __expf(v0.z - mx) * sc[m*8+2];
            u[3] = __expf(v0.w - mx) * sc[m*8+3];
            u[4] = __expf(v1.x - mx) * sc[m*8+4];
            u[5] = __expf(v1.y - mx) * sc[m*8+5];
            u[6] = __expf(v1.z - mx) * sc[m*8+6];
            u[7] = __expf(v1.w - mx) * sc[m*8+7];
            A0 += u[0] + u[4]; A1 += u[1] + u[5];
            A2 += u[2] + u[6]; A3 += u[3] + u[7];
            #pragma unroll
            for (int t = 0; t < 8; t++) {
                float uu = u[t];
                float jj = (float)(m * 8 + t);
                bool g1 = uu > m1;            // strict > keeps earliest index on ties
                bool g2 = uu > m2;
                m2 = g1 ? m1 : (g2 ? uu : m2);
                i2 = g1 ? i1 : (g2 ? jj : i2);
                m1 = g1 ? uu : m1;
                i1 = g1 ? jj : i1;
            }
        }
        float A  = (A0 + A1) + (A2 + A3);
        float ri = g_r[row];
        float t  = __fdividef(ri, fmaf(ri, A, EPSF));
        float v1v = m1 * t, v2v = m2 * t;      // top-2 of row-normalized q
        float inv = __fdividef(1.0f, v1v + v2v + EPSF);
        reinterpret_cast<float2*>(out)[row]            = make_float2(i1, i2);
        reinterpret_cast<float2*>(out)[(size_t)S + row] = make_float2(v1v * inv, v2v * inv);
    }
}

// ---------------------------------------------------------------------------
// Generic fallback (k != 2): warp-per-row, shuffle top-k (known-correct R3 code)
// ---------------------------------------------------------------------------
__global__ void k_final_gen(const float* __restrict__ logits,
                            float* __restrict__ out, int S, int k, size_t out_n) {
    int lane = threadIdx.x & 31;
    int warp = (blockIdx.x * blockDim.x + threadIdx.x) >> 5;
    int nw   = (gridDim.x * blockDim.x) >> 5;
    float2 cc = ((const float2*)g_c)[lane];

    for (int row = warp; row < S; row += nw) {
        float2 x = ((const float2*)logits)[(size_t)row * 32 + lane];
        float m = fmaxf(x.x, x.y);
        #pragma unroll
        for (int o = 16; o; o >>= 1) m = fmaxf(m, __shfl_xor_sync(0xFFFFFFFFu, m, o));
        float u0 = __expf(x.x - m) * cc.x;
        float u1 = __expf(x.y - m) * cc.y;
        float A = u0 + u1;
        #pragma unroll
        for (int o = 16; o; o >>= 1) A += __shfl_xor_sync(0xFFFFFFFFu, A, o);
        float ri = g_r[row];
        float denom = ri * A + EPSF;
        float lu0 = u0, lu1 = u1;
        float vals[8]; int idxs[8];
        for (int t = 0; t < k; t++) {
            float lv; int li;
            if (lu0 >= lu1) { lv = lu0; li = 2 * lane; }
            else            { lv = lu1; li = 2 * lane + 1; }
            #pragma unroll
            for (int o = 16; o; o >>= 1) {
                float ov = __shfl_xor_sync(0xFFFFFFFFu, lv, o);
                int   oi = __shfl_xor_sync(0xFFFFFFFFu, li, o);
                if (ov > lv || (ov == lv && oi < li)) { lv = ov; li = oi; }
            }
            vals[t] = lv; idxs[t] = li;
            if (li == 2 * lane)     lu0 = -1.f;
            if (li == 2 * lane + 1) lu1 = -1.f;
        }
        if (lane == 0) {
            float v[8], vs = 0.f;
            for (int t = 0; t < k; t++) { v[t] = ri * vals[t] / denom; vs += v[t]; }
            float inv = 1.0f / (vs + EPSF);
            for (int t = 0; t < k; t++) {
                size_t pi = (size_t)row * k + t;
                size_t pw = (size_t)S * k + pi;
                if (pi < out_n) out[pi] = (float)idxs[t];
                if (pw < out_n) out[pw] = v[t] * inv;
            }
        }
    }
}

// ---------------------------------------------------------------------------
extern "C" void kernel_launch(void* const* d_in, const int* in_sizes, int n_in,
                              void* d_out, int out_size) {
    const float* logits = (const float*)d_in[0];
    float*       out    = (float*)d_out;

    int S = in_sizes[0] / EXPERTS;
    if (S > S_MAX) S = S_MAX;
    if (S < 1) S = 1;
    float col_target = (float)S / (float)EXPERTS;

    int k = (int)((size_t)out_size / (2 * (size_t)S));
    if (k < 1) k = 1;
    if (k > 8) k = 8;

    k_prep<<<NB, NT>>>(logits, S, col_target);          // includes iteration 1
    for (int it = 1; it < 10; it++)
        k_iter<<<NB, NT>>>(S, col_target);              // iterations 2..10
    if (k == 2)
        k_final2<<<NB, NT>>>(logits, out, S);
    else
        k_final_gen<<<4096, 256>>>(logits, out, S, k, (size_t)out_size);
}

// round 5
// speedup vs baseline: 1.5238x; 1.4102x over previous
#include <cuda_runtime.h>
#include <cuda_fp16.h>

#define EPSF 1e-6f
#define EXPERTS 64
#define S_MAX 524288
#define NB 512
#define NT 256

// Scratch (static device allocations)
__device__ __half2 g_e[(size_t)S_MAX * 32];      // exp(logits - rowmax) fp16, 64MB (128B/row)
__device__ float   g_r[S_MAX];                   // row scale
__device__ __align__(16) float g_c[EXPERTS];     // col scale
__device__ float   g_bpart[EXPERTS * NB];        // per-block column partials
__device__ unsigned g_tick;                      // last-block ticket (zero-init, self-reset)

__device__ __forceinline__ float2 h2f(unsigned u) {
    __half2 h = *reinterpret_cast<__half2*>(&u);
    return __half22float2(h);
}
__device__ __forceinline__ unsigned f2h2(float a, float b) {
    __half2 h = __floats2half2_rn(a, b);
    return *reinterpret_cast<unsigned*>(&h);
}

// Block tail: combine per-thread column partials (thread layout: lane&3 == q
// owns cols q*16..q*16+15, replicated across the 8 quad-groups of the warp),
// write per-block partials, last block reduces + updates g_c.
__device__ __forceinline__ void tail_update(const float* b, float col_target,
                                            bool first) {
    __shared__ float sb[NT / 32][EXPERTS];
    __shared__ float sq[4][EXPERTS];
    __shared__ int   slast;
    int tid = threadIdx.x, lane = tid & 31, wid = tid >> 5;

    if (lane < 4) {
        #pragma unroll
        for (int i = 0; i < 16; i++) sb[wid][lane * 16 + i] = b[i];
    }
    __syncthreads();
    if (tid < EXPERTS) {
        float s = 0.f;
        #pragma unroll
        for (int w = 0; w < NT / 32; w++) s += sb[w][tid];
        g_bpart[tid * NB + blockIdx.x] = s;
    }
    __threadfence();
    if (tid == 0) {
        unsigned t = atomicAdd(&g_tick, 1u);
        slast = (t == NB - 1) ? 1 : 0;
    }
    __syncthreads();
    if (!slast) return;

    int col = tid & 63, qq = tid >> 6;
    float s = 0.f;
    for (int p = qq * (NB / 4); p < (qq + 1) * (NB / 4); p++)
        s += g_bpart[col * NB + p];
    sq[qq][col] = s;
    __syncthreads();
    if (tid < EXPERTS) {
        float btot = sq[0][tid] + sq[1][tid] + sq[2][tid] + sq[3][tid];
        float c = first ? 1.0f : g_c[tid];
        g_c[tid] = c * col_target / (c * btot + EPSF);
    }
    if (tid == 0) g_tick = 0;
}

// ---------------------------------------------------------------------------
// K1: prep + Sinkhorn iteration 1 fused. Quad-split: 4 threads per 4 rows,
// thread q handles columns [q*16, q*16+16).
// ---------------------------------------------------------------------------
__global__ __launch_bounds__(NT, 2) void k_prep(const float* __restrict__ logits,
                                                int S, float col_target) {
    int tid = threadIdx.x, lane = tid & 31, q = lane & 3;
    float b[16];
    #pragma unroll
    for (int i = 0; i < 16; i++) b[i] = 0.f;

    int gq = (blockIdx.x * NT + tid) >> 2;   // global quad id
    int nq = (NB * NT) >> 2;

    for (int rb = gq * 4; rb < S; rb += nq * 4) {
        #pragma unroll
        for (int r = 0; r < 4; r++) {
            int row = rb + r;
            if (row >= S) break;
            const float4* xp = reinterpret_cast<const float4*>(logits)
                               + (size_t)row * 16 + q * 4;
            float4 v0 = xp[0], v1 = xp[1], v2 = xp[2], v3 = xp[3];
            float mx = fmaxf(fmaxf(fmaxf(v0.x, v0.y), fmaxf(v0.z, v0.w)),
                             fmaxf(fmaxf(v1.x, v1.y), fmaxf(v1.z, v1.w)));
            mx = fmaxf(mx, fmaxf(fmaxf(v2.x, v2.y), fmaxf(v2.z, v2.w)));
            mx = fmaxf(mx, fmaxf(fmaxf(v3.x, v3.y), fmaxf(v3.z, v3.w)));
            mx = fmaxf(mx, __shfl_xor_sync(0xFFFFFFFFu, mx, 1));
            mx = fmaxf(mx, __shfl_xor_sync(0xFFFFFFFFu, mx, 2));

            float f[16];
            f[0] = __expf(v0.x - mx); f[1] = __expf(v0.y - mx);
            f[2] = __expf(v0.z - mx); f[3] = __expf(v0.w - mx);
            f[4] = __expf(v1.x - mx); f[5] = __expf(v1.y - mx);
            f[6] = __expf(v1.z - mx); f[7] = __expf(v1.w - mx);
            f[8]  = __expf(v2.x - mx); f[9]  = __expf(v2.y - mx);
            f[10] = __expf(v2.z - mx); f[11] = __expf(v2.w - mx);
            f[12] = __expf(v3.x - mx); f[13] = __expf(v3.y - mx);
            f[14] = __expf(v3.z - mx); f[15] = __expf(v3.w - mx);

            float a = 0.f;
            #pragma unroll
            for (int i = 0; i < 16; i++) a += f[i];
            a += __shfl_xor_sync(0xFFFFFFFFu, a, 1);
            a += __shfl_xor_sync(0xFFFFFFFFu, a, 2);

            uint4 e0, e1;
            e0.x = f2h2(f[0], f[1]);   e0.y = f2h2(f[2], f[3]);
            e0.z = f2h2(f[4], f[5]);   e0.w = f2h2(f[6], f[7]);
            e1.x = f2h2(f[8], f[9]);   e1.y = f2h2(f[10], f[11]);
            e1.z = f2h2(f[12], f[13]); e1.w = f2h2(f[14], f[15]);
            uint4* dp = reinterpret_cast<uint4*>(g_e) + (size_t)row * 8 + q * 2;
            dp[0] = e0; dp[1] = e1;

            float rn = __fdividef(1.0f, a + EPSF);
            if (q == r) g_r[row] = rn;
            #pragma unroll
            for (int i = 0; i < 16; i++) b[i] = fmaf(f[i], rn, b[i]);
        }
    }
    // Fold across the 8 quad-groups of the warp (same-q lanes share columns).
    #pragma unroll
    for (int o = 4; o < 32; o <<= 1)
        #pragma unroll
        for (int i = 0; i < 16; i++)
            b[i] += __shfl_xor_sync(0xFFFFFFFFu, b[i], o);
    tail_update(b, col_target, true);
}

// ---------------------------------------------------------------------------
// K2: one Sinkhorn iteration, quad-split.
// ---------------------------------------------------------------------------
__global__ __launch_bounds__(NT, 2) void k_iter(int S, float col_target) {
    __shared__ __align__(16) float sc[EXPERTS];
    int tid = threadIdx.x, lane = tid & 31, q = lane & 3;
    if (tid < EXPERTS) sc[tid] = g_c[tid];
    __syncthreads();

    float cq[16];
    #pragma unroll
    for (int i = 0; i < 16; i++) cq[i] = sc[q * 16 + i];

    float b[16];
    #pragma unroll
    for (int i = 0; i < 16; i++) b[i] = 0.f;

    int gq = (blockIdx.x * NT + tid) >> 2;
    int nq = (NB * NT) >> 2;

    for (int rb = gq * 4; rb < S; rb += nq * 4) {
        uint4 e[4][2];
        float ap[4];
        #pragma unroll
        for (int r = 0; r < 4; r++) {
            const uint4* ep = reinterpret_cast<const uint4*>(g_e)
                              + (size_t)(rb + r) * 8 + q * 2;
            e[r][0] = ep[0]; e[r][1] = ep[1];
            float a = 0.f;
            float2 f;
            f = h2f(e[r][0].x); a = fmaf(f.x, cq[0], a);  a = fmaf(f.y, cq[1], a);
            f = h2f(e[r][0].y); a = fmaf(f.x, cq[2], a);  a = fmaf(f.y, cq[3], a);
            f = h2f(e[r][0].z); a = fmaf(f.x, cq[4], a);  a = fmaf(f.y, cq[5], a);
            f = h2f(e[r][0].w); a = fmaf(f.x, cq[6], a);  a = fmaf(f.y, cq[7], a);
            f = h2f(e[r][1].x); a = fmaf(f.x, cq[8], a);  a = fmaf(f.y, cq[9], a);
            f = h2f(e[r][1].y); a = fmaf(f.x, cq[10], a); a = fmaf(f.y, cq[11], a);
            f = h2f(e[r][1].z); a = fmaf(f.x, cq[12], a); a = fmaf(f.y, cq[13], a);
            f = h2f(e[r][1].w); a = fmaf(f.x, cq[14], a); a = fmaf(f.y, cq[15], a);
            ap[r] = a;
        }
        #pragma unroll
        for (int r = 0; r < 4; r++) {
            ap[r] += __shfl_xor_sync(0xFFFFFFFFu, ap[r], 1);
            ap[r] += __shfl_xor_sync(0xFFFFFFFFu, ap[r], 2);
        }
        #pragma unroll
        for (int r = 0; r < 4; r++) {
            float ri = g_r[rb + r];
            float rn = __fdividef(ri, fmaf(ri, ap[r], EPSF));
            if (q == r) g_r[rb + r] = rn;
            float2 f;
            f = h2f(e[r][0].x); b[0]  = fmaf(f.x, rn, b[0]);  b[1]  = fmaf(f.y, rn, b[1]);
            f = h2f(e[r][0].y); b[2]  = fmaf(f.x, rn, b[2]);  b[3]  = fmaf(f.y, rn, b[3]);
            f = h2f(e[r][0].z); b[4]  = fmaf(f.x, rn, b[4]);  b[5]  = fmaf(f.y, rn, b[5]);
            f = h2f(e[r][0].w); b[6]  = fmaf(f.x, rn, b[6]);  b[7]  = fmaf(f.y, rn, b[7]);
            f = h2f(e[r][1].x); b[8]  = fmaf(f.x, rn, b[8]);  b[9]  = fmaf(f.y, rn, b[9]);
            f = h2f(e[r][1].y); b[10] = fmaf(f.x, rn, b[10]); b[11] = fmaf(f.y, rn, b[11]);
            f = h2f(e[r][1].z); b[12] = fmaf(f.x, rn, b[12]); b[13] = fmaf(f.y, rn, b[13]);
            f = h2f(e[r][1].w); b[14] = fmaf(f.x, rn, b[14]); b[15] = fmaf(f.y, rn, b[15]);
        }
    }
    #pragma unroll
    for (int o = 4; o < 32; o <<= 1)
        #pragma unroll
        for (int i = 0; i < 16; i++)
            b[i] += __shfl_xor_sync(0xFFFFFFFFu, b[i], o);
    tail_update(b, col_target, false);
}

// ---------------------------------------------------------------------------
// K3: final (k == 2 fast path). Quad-split; fp32 ranking from logits.
// Output float32: [idx (S*2)] then [weights (S*2)].
// ---------------------------------------------------------------------------
__global__ __launch_bounds__(NT, 2) void k_final2(const float* __restrict__ logits,
                                                  float* __restrict__ out, int S) {
    __shared__ __align__(16) float sc[EXPERTS];
    int tid = threadIdx.x, lane = tid & 31, q = lane & 3;
    if (tid < EXPERTS) sc[tid] = g_c[tid];
    __syncthreads();

    float cq[16];
    #pragma unroll
    for (int i = 0; i < 16; i++) cq[i] = sc[q * 16 + i];

    int gq = (blockIdx.x * NT + tid) >> 2;
    int nq = (NB * NT) >> 2;

    for (int rb = gq * 4; rb < S; rb += nq * 4) {
        #pragma unroll
        for (int r = 0; r < 4; r++) {
            int row = rb + r;
            if (row >= S) break;
            const float4* xp = reinterpret_cast<const float4*>(logits)
                               + (size_t)row * 16 + q * 4;
            float4 v0 = xp[0], v1 = xp[1], v2 = xp[2], v3 = xp[3];
            float mx = fmaxf(fmaxf(fmaxf(v0.x, v0.y), fmaxf(v0.z, v0.w)),
                             fmaxf(fmaxf(v1.x, v1.y), fmaxf(v1.z, v1.w)));
            mx = fmaxf(mx, fmaxf(fmaxf(v2.x, v2.y), fmaxf(v2.z, v2.w)));
            mx = fmaxf(mx, fmaxf(fmaxf(v3.x, v3.y), fmaxf(v3.z, v3.w)));
            mx = fmaxf(mx, __shfl_xor_sync(0xFFFFFFFFu, mx, 1));
            mx = fmaxf(mx, __shfl_xor_sync(0xFFFFFFFFu, mx, 2));

            float u[16];
            u[0]  = __expf(v0.x - mx) * cq[0];  u[1]  = __expf(v0.y - mx) * cq[1];
            u[2]  = __expf(v0.z - mx) * cq[2];  u[3]  = __expf(v0.w - mx) * cq[3];
            u[4]  = __expf(v1.x - mx) * cq[4];  u[5]  = __expf(v1.y - mx) * cq[5];
            u[6]  = __expf(v1.z - mx) * cq[6];  u[7]  = __expf(v1.w - mx) * cq[7];
            u[8]  = __expf(v2.x - mx) * cq[8];  u[9]  = __expf(v2.y - mx) * cq[9];
            u[10] = __expf(v2.z - mx) * cq[10]; u[11] = __expf(v2.w - mx) * cq[11];
            u[12] = __expf(v3.x - mx) * cq[12]; u[13] = __expf(v3.y - mx) * cq[13];
            u[14] = __expf(v3.z - mx) * cq[14]; u[15] = __expf(v3.w - mx) * cq[15];

            float A = 0.f;
            float m1 = -1.f, m2 = -1.f, i1 = 0.f, i2 = 0.f;
            #pragma unroll
            for (int t = 0; t < 16; t++) {
                A += u[t];
                float jj = (float)(q * 16 + t);
                bool g1 = u[t] > m1, g2 = u[t] > m2;
                m2 = g1 ? m1 : (g2 ? u[t] : m2);
                i2 = g1 ? i1 : (g2 ? jj : i2);
                m1 = g1 ? u[t] : m1;
                i1 = g1 ? jj : i1;
            }
            A += __shfl_xor_sync(0xFFFFFFFFu, A, 1);
            A += __shfl_xor_sync(0xFFFFFFFFu, A, 2);

            // merge top-2 across the quad
            #pragma unroll
            for (int o = 1; o <= 2; o <<= 1) {
                float om1 = __shfl_xor_sync(0xFFFFFFFFu, m1, o);
                float oi1 = __shfl_xor_sync(0xFFFFFFFFu, i1, o);
                float om2 = __shfl_xor_sync(0xFFFFFFFFu, m2, o);
                float oi2 = __shfl_xor_sync(0xFFFFFFFFu, i2, o);
                if (om1 > m1) {
                    bool keep = (m1 >= om2);
                    m2 = keep ? m1 : om2;
                    i2 = keep ? i1 : oi2;
                    m1 = om1; i1 = oi1;
                } else if (om1 > m2) {
                    m2 = om1; i2 = oi1;
                }
            }

            if (q == r) {
                float ri  = g_r[row];
                float t   = __fdividef(ri, fmaf(ri, A, EPSF));
                float w1  = m1 * t, w2 = m2 * t;
                float inv = __fdividef(1.0f, w1 + w2 + EPSF);
                reinterpret_cast<float2*>(out)[row] = make_float2(i1, i2);
                reinterpret_cast<float2*>(out)[(size_t)S + row] =
                    make_float2(w1 * inv, w2 * inv);
            }
        }
    }
}

// ---------------------------------------------------------------------------
// Generic fallback (k != 2): warp-per-row (known-correct R3 code)
// ---------------------------------------------------------------------------
__global__ void k_final_gen(const float* __restrict__ logits,
                            float* __restrict__ out, int S, int k, size_t out_n) {
    int lane = threadIdx.x & 31;
    int warp = (blockIdx.x * blockDim.x + threadIdx.x) >> 5;
    int nw   = (gridDim.x * blockDim.x) >> 5;
    float2 cc = ((const float2*)g_c)[lane];

    for (int row = warp; row < S; row += nw) {
        float2 x = ((const float2*)logits)[(size_t)row * 32 + lane];
        float m = fmaxf(x.x, x.y);
        #pragma unroll
        for (int o = 16; o; o >>= 1) m = fmaxf(m, __shfl_xor_sync(0xFFFFFFFFu, m, o));
        float u0 = __expf(x.x - m) * cc.x;
        float u1 = __expf(x.y - m) * cc.y;
        float A = u0 + u1;
        #pragma unroll
        for (int o = 16; o; o >>= 1) A += __shfl_xor_sync(0xFFFFFFFFu, A, o);
        float ri = g_r[row];
        float denom = ri * A + EPSF;
        float lu0 = u0, lu1 = u1;
        float vals[8]; int idxs[8];
        for (int t = 0; t < k; t++) {
            float lv; int li;
            if (lu0 >= lu1) { lv = lu0; li = 2 * lane; }
            else            { lv = lu1; li = 2 * lane + 1; }
            #pragma unroll
            for (int o = 16; o; o >>= 1) {
                float ov = __shfl_xor_sync(0xFFFFFFFFu, lv, o);
                int   oi = __shfl_xor_sync(0xFFFFFFFFu, li, o);
                if (ov > lv || (ov == lv && oi < li)) { lv = ov; li = oi; }
            }
            vals[t] = lv; idxs[t] = li;
            if (li == 2 * lane)     lu0 = -1.f;
            if (li == 2 * lane + 1) lu1 = -1.f;
        }
        if (lane == 0) {
            float v[8], vs = 0.f;
            for (int t = 0; t < k; t++) { v[t] = ri * vals[t] / denom; vs += v[t]; }
            float inv = 1.0f / (vs + EPSF);
            for (int t = 0; t < k; t++) {
                size_t pi = (size_t)row * k + t;
                size_t pw = (size_t)S * k + pi;
                if (pi < out_n) out[pi] = (float)idxs[t];
                if (pw < out_n) out[pw] = v[t] * inv;
            }
        }
    }
}

// ---------------------------------------------------------------------------
extern "C" void kernel_launch(void* const* d_in, const int* in_sizes, int n_in,
                              void* d_out, int out_size) {
    const float* logits = (const float*)d_in[0];
    float*       out    = (float*)d_out;

    int S = in_sizes[0] / EXPERTS;
    if (S > S_MAX) S = S_MAX;
    if (S < 1) S = 1;
    float col_target = (float)S / (float)EXPERTS;

    int k = (int)((size_t)out_size / (2 * (size_t)S));
    if (k < 1) k = 1;
    if (k > 8) k = 8;

    k_prep<<<NB, NT>>>(logits, S, col_target);          // includes iteration 1
    for (int it = 1; it < 10; it++)
        k_iter<<<NB, NT>>>(S, col_target);              // iterations 2..10
    if (k == 2)
        k_final2<<<NB, NT>>>(logits, out, S);
    else
        k_final_gen<<<4096, 256>>>(logits, out, S, k, (size_t)out_size);
}

// round 6
// speedup vs baseline: 2.1628x; 1.4193x over previous
#include <cuda_runtime.h>
#include <cuda_fp16.h>

#define EPSF 1e-6f
#define EXPERTS 64
#define S_MAX 524288
#define NB 456          // 3 CTAs/SM x 152 SMs, divisible by 4
#define NT 256

// Scratch (static device allocations)
__device__ __half2 g_e[(size_t)S_MAX * 32];      // exp(logits - rowmax) fp16, 64MB (128B/row)
__device__ float   g_r[S_MAX];                   // row scale
__device__ __align__(16) float g_c[EXPERTS];     // col scale
__device__ float   g_bpart[EXPERTS * NB];        // per-block column partials
__device__ unsigned g_tick;                      // last-block ticket (zero-init, self-reset)

__device__ __forceinline__ float2 h2f(unsigned u) {
    __half2 h = *reinterpret_cast<__half2*>(&u);
    return __half22float2(h);
}
__device__ __forceinline__ unsigned f2h2(float a, float b) {
    __half2 h = __floats2half2_rn(a, b);
    return *reinterpret_cast<unsigned*>(&h);
}
// dot of 16 fp16 (two uint4) with cq[16]
__device__ __forceinline__ float dot16(uint4 u0, uint4 u1, const float* cq) {
    float a = 0.f; float2 f;
    f = h2f(u0.x); a = fmaf(f.x, cq[0], a);  a = fmaf(f.y, cq[1], a);
    f = h2f(u0.y); a = fmaf(f.x, cq[2], a);  a = fmaf(f.y, cq[3], a);
    f = h2f(u0.z); a = fmaf(f.x, cq[4], a);  a = fmaf(f.y, cq[5], a);
    f = h2f(u0.w); a = fmaf(f.x, cq[6], a);  a = fmaf(f.y, cq[7], a);
    f = h2f(u1.x); a = fmaf(f.x, cq[8], a);  a = fmaf(f.y, cq[9], a);
    f = h2f(u1.y); a = fmaf(f.x, cq[10], a); a = fmaf(f.y, cq[11], a);
    f = h2f(u1.z); a = fmaf(f.x, cq[12], a); a = fmaf(f.y, cq[13], a);
    f = h2f(u1.w); a = fmaf(f.x, cq[14], a); a = fmaf(f.y, cq[15], a);
    return a;
}
// b[i] += e[i] * rn for 16 fp16
__device__ __forceinline__ void acc16(uint4 u0, uint4 u1, float rn, float* b) {
    float2 f;
    f = h2f(u0.x); b[0]  = fmaf(f.x, rn, b[0]);  b[1]  = fmaf(f.y, rn, b[1]);
    f = h2f(u0.y); b[2]  = fmaf(f.x, rn, b[2]);  b[3]  = fmaf(f.y, rn, b[3]);
    f = h2f(u0.z); b[4]  = fmaf(f.x, rn, b[4]);  b[5]  = fmaf(f.y, rn, b[5]);
    f = h2f(u0.w); b[6]  = fmaf(f.x, rn, b[6]);  b[7]  = fmaf(f.y, rn, b[7]);
    f = h2f(u1.x); b[8]  = fmaf(f.x, rn, b[8]);  b[9]  = fmaf(f.y, rn, b[9]);
    f = h2f(u1.y); b[10] = fmaf(f.x, rn, b[10]); b[11] = fmaf(f.y, rn, b[11]);
    f = h2f(u1.z); b[12] = fmaf(f.x, rn, b[12]); b[13] = fmaf(f.y, rn, b[13]);
    f = h2f(u1.w); b[14] = fmaf(f.x, rn, b[14]); b[15] = fmaf(f.y, rn, b[15]);
}

// Block tail: combine per-thread column partials (thread q of each quad owns
// cols q*16..q*16+15, replicated across the 8 quads of the warp), write
// per-block partials, last block reduces + updates g_c.
__device__ __forceinline__ void tail_update(const float* b, float col_target,
                                            bool first) {
    __shared__ float sb[NT / 32][EXPERTS];
    __shared__ float sq[4][EXPERTS];
    __shared__ int   slast;
    int tid = threadIdx.x, lane = tid & 31, wid = tid >> 5;

    if (lane < 4) {
        #pragma unroll
        for (int i = 0; i < 16; i++) sb[wid][lane * 16 + i] = b[i];
    }
    __syncthreads();
    if (tid < EXPERTS) {
        float s = 0.f;
        #pragma unroll
        for (int w = 0; w < NT / 32; w++) s += sb[w][tid];
        g_bpart[tid * NB + blockIdx.x] = s;
    }
    __threadfence();
    if (tid == 0) {
        unsigned t = atomicAdd(&g_tick, 1u);
        slast = (t == NB - 1) ? 1 : 0;
    }
    __syncthreads();
    if (!slast) return;

    int col = tid & 63, qq = tid >> 6;
    float s = 0.f;
    for (int p = qq * (NB / 4); p < (qq + 1) * (NB / 4); p++)
        s += g_bpart[col * NB + p];
    sq[qq][col] = s;
    __syncthreads();
    if (tid < EXPERTS) {
        float btot = sq[0][tid] + sq[1][tid] + sq[2][tid] + sq[3][tid];
        float c = first ? 1.0f : g_c[tid];
        g_c[tid] = c * col_target / (c * btot + EPSF);
    }
    if (tid == 0) g_tick = 0;
}

// ---------------------------------------------------------------------------
// K1: prep + Sinkhorn iteration 1 fused. Quad-split: 4 threads per row,
// thread q handles columns [q*16, q*16+16). Logits read with streaming hint.
// ---------------------------------------------------------------------------
__global__ __launch_bounds__(NT, 3) void k_prep(const float* __restrict__ logits,
                                                int S, float col_target) {
    int tid = threadIdx.x, lane = tid & 31, q = lane & 3;
    float b[16];
    #pragma unroll
    for (int i = 0; i < 16; i++) b[i] = 0.f;

    int gq = (blockIdx.x * NT + tid) >> 2;   // global quad id
    int nq = (NB * NT) >> 2;

    for (int row = gq; row < S; row += nq) {
        const float4* xp = reinterpret_cast<const float4*>(logits)
                           + (size_t)row * 16 + q * 4;
        float4 v0 = __ldcs(xp + 0), v1 = __ldcs(xp + 1);
        float4 v2 = __ldcs(xp + 2), v3 = __ldcs(xp + 3);
        float mx = fmaxf(fmaxf(fmaxf(v0.x, v0.y), fmaxf(v0.z, v0.w)),
                         fmaxf(fmaxf(v1.x, v1.y), fmaxf(v1.z, v1.w)));
        mx = fmaxf(mx, fmaxf(fmaxf(v2.x, v2.y), fmaxf(v2.z, v2.w)));
        mx = fmaxf(mx, fmaxf(fmaxf(v3.x, v3.y), fmaxf(v3.z, v3.w)));
        mx = fmaxf(mx, __shfl_xor_sync(0xFFFFFFFFu, mx, 1));
        mx = fmaxf(mx, __shfl_xor_sync(0xFFFFFFFFu, mx, 2));

        float f[16];
        f[0]  = __expf(v0.x - mx); f[1]  = __expf(v0.y - mx);
        f[2]  = __expf(v0.z - mx); f[3]  = __expf(v0.w - mx);
        f[4]  = __expf(v1.x - mx); f[5]  = __expf(v1.y - mx);
        f[6]  = __expf(v1.z - mx); f[7]  = __expf(v1.w - mx);
        f[8]  = __expf(v2.x - mx); f[9]  = __expf(v2.y - mx);
        f[10] = __expf(v2.z - mx); f[11] = __expf(v2.w - mx);
        f[12] = __expf(v3.x - mx); f[13] = __expf(v3.y - mx);
        f[14] = __expf(v3.z - mx); f[15] = __expf(v3.w - mx);

        float a = 0.f;
        #pragma unroll
        for (int i = 0; i < 16; i++) a += f[i];
        a += __shfl_xor_sync(0xFFFFFFFFu, a, 1);
        a += __shfl_xor_sync(0xFFFFFFFFu, a, 2);

        uint4 e0, e1;
        e0.x = f2h2(f[0], f[1]);   e0.y = f2h2(f[2], f[3]);
        e0.z = f2h2(f[4], f[5]);   e0.w = f2h2(f[6], f[7]);
        e1.x = f2h2(f[8], f[9]);   e1.y = f2h2(f[10], f[11]);
        e1.z = f2h2(f[12], f[13]); e1.w = f2h2(f[14], f[15]);
        uint4* dp = reinterpret_cast<uint4*>(g_e) + (size_t)row * 8 + q * 2;
        dp[0] = e0; dp[1] = e1;

        float rn = __fdividef(1.0f, a + EPSF);
        if (q == 0) g_r[row] = rn;
        // accumulate b from the packed halves (matches what iterations read)
        acc16(e0, e1, rn, b);
    }
    // fold across the 8 quads of the warp (same-q lanes share columns)
    #pragma unroll
    for (int o = 4; o < 32; o <<= 1)
        #pragma unroll
        for (int i = 0; i < 16; i++)
            b[i] += __shfl_xor_sync(0xFFFFFFFFu, b[i], o);
    tail_update(b, col_target, true);
}

// ---------------------------------------------------------------------------
// K2: one Sinkhorn iteration, quad-split, 2 rows per loop step (MLP=4).
// ---------------------------------------------------------------------------
__global__ __launch_bounds__(NT, 3) void k_iter(int S, float col_target) {
    __shared__ __align__(16) float sc[EXPERTS];
    int tid = threadIdx.x, lane = tid & 31, q = lane & 3;
    if (tid < EXPERTS) sc[tid] = g_c[tid];
    __syncthreads();

    float cq[16];
    #pragma unroll
    for (int i = 0; i < 16; i++) cq[i] = sc[q * 16 + i];

    float b[16];
    #pragma unroll
    for (int i = 0; i < 16; i++) b[i] = 0.f;

    int gq = (blockIdx.x * NT + tid) >> 2;
    int nq = (NB * NT) >> 2;

    for (int rb = gq * 2; rb < S; rb += nq * 2) {
        const uint4* ep = reinterpret_cast<const uint4*>(g_e)
                          + (size_t)rb * 8 + q * 2;
        uint4 ea0 = ep[0], ea1 = ep[1];
        bool  has2 = (rb + 1) < S;
        uint4 eb0, eb1;
        if (has2) { eb0 = ep[8]; eb1 = ep[9]; }

        float a0 = dot16(ea0, ea1, cq);
        float a1 = has2 ? dot16(eb0, eb1, cq) : 0.f;
        a0 += __shfl_xor_sync(0xFFFFFFFFu, a0, 1);
        a0 += __shfl_xor_sync(0xFFFFFFFFu, a0, 2);
        a1 += __shfl_xor_sync(0xFFFFFFFFu, a1, 1);
        a1 += __shfl_xor_sync(0xFFFFFFFFu, a1, 2);

        float r0 = g_r[rb];
        float rn0 = __fdividef(r0, fmaf(r0, a0, EPSF));
        if (q == 0) g_r[rb] = rn0;
        acc16(ea0, ea1, rn0, b);

        if (has2) {
            float r1 = g_r[rb + 1];
            float rn1 = __fdividef(r1, fmaf(r1, a1, EPSF));
            if (q == 1) g_r[rb + 1] = rn1;
            acc16(eb0, eb1, rn1, b);
        }
    }
    #pragma unroll
    for (int o = 4; o < 32; o <<= 1)
        #pragma unroll
        for (int i = 0; i < 16; i++)
            b[i] += __shfl_xor_sync(0xFFFFFFFFu, b[i], o);
    tail_update(b, col_target, false);
}

// ---------------------------------------------------------------------------
// K3: final (k == 2 fast path). Quad-split; fp32 ranking from logits (ldcs).
// Output float32: [idx (S*2)] then [weights (S*2)].
// ---------------------------------------------------------------------------
__global__ __launch_bounds__(NT, 3) void k_final2(const float* __restrict__ logits,
                                                  float* __restrict__ out, int S) {
    __shared__ __align__(16) float sc[EXPERTS];
    int tid = threadIdx.x, lane = tid & 31, q = lane & 3;
    if (tid < EXPERTS) sc[tid] = g_c[tid];
    __syncthreads();

    float cq[16];
    #pragma unroll
    for (int i = 0; i < 16; i++) cq[i] = sc[q * 16 + i];

    int gq = (blockIdx.x * NT + tid) >> 2;
    int nq = (NB * NT) >> 2;

    for (int row = gq; row < S; row += nq) {
        const float4* xp = reinterpret_cast<const float4*>(logits)
                           + (size_t)row * 16 + q * 4;
        float4 v0 = __ldcs(xp + 0), v1 = __ldcs(xp + 1);
        float4 v2 = __ldcs(xp + 2), v3 = __ldcs(xp + 3);
        float mx = fmaxf(fmaxf(fmaxf(v0.x, v0.y), fmaxf(v0.z, v0.w)),
                         fmaxf(fmaxf(v1.x, v1.y), fmaxf(v1.z, v1.w)));
        mx = fmaxf(mx, fmaxf(fmaxf(v2.x, v2.y), fmaxf(v2.z, v2.w)));
        mx = fmaxf(mx, fmaxf(fmaxf(v3.x, v3.y), fmaxf(v3.z, v3.w)));
        mx = fmaxf(mx, __shfl_xor_sync(0xFFFFFFFFu, mx, 1));
        mx = fmaxf(mx, __shfl_xor_sync(0xFFFFFFFFu, mx, 2));

        float u[16];
        u[0]  = __expf(v0.x - mx) * cq[0];  u[1]  = __expf(v0.y - mx) * cq[1];
        u[2]  = __expf(v0.z - mx) * cq[2];  u[3]  = __expf(v0.w - mx) * cq[3];
        u[4]  = __expf(v1.x - mx) * cq[4];  u[5]  = __expf(v1.y - mx) * cq[5];
        u[6]  = __expf(v1.z - mx) * cq[6];  u[7]  = __expf(v1.w - mx) * cq[7];
        u[8]  = __expf(v2.x - mx) * cq[8];  u[9]  = __expf(v2.y - mx) * cq[9];
        u[10] = __expf(v2.z - mx) * cq[10]; u[11] = __expf(v2.w - mx) * cq[11];
        u[12] = __expf(v3.x - mx) * cq[12]; u[13] = __expf(v3.y - mx) * cq[13];
        u[14] = __expf(v3.z - mx) * cq[14]; u[15] = __expf(v3.w - mx) * cq[15];

        float A = 0.f;
        float m1 = -1.f, m2 = -1.f, i1 = 0.f, i2 = 0.f;
        #pragma unroll
        for (int t = 0; t < 16; t++) {
            A += u[t];
            float jj = (float)(q * 16 + t);
            bool g1 = u[t] > m1, g2 = u[t] > m2;
            m2 = g1 ? m1 : (g2 ? u[t] : m2);
            i2 = g1 ? i1 : (g2 ? jj : i2);
            m1 = g1 ? u[t] : m1;
            i1 = g1 ? jj : i1;
        }
        A += __shfl_xor_sync(0xFFFFFFFFu, A, 1);
        A += __shfl_xor_sync(0xFFFFFFFFu, A, 2);

        // merge top-2 across the quad
        #pragma unroll
        for (int o = 1; o <= 2; o <<= 1) {
            float om1 = __shfl_xor_sync(0xFFFFFFFFu, m1, o);
            float oi1 = __shfl_xor_sync(0xFFFFFFFFu, i1, o);
            float om2 = __shfl_xor_sync(0xFFFFFFFFu, m2, o);
            float oi2 = __shfl_xor_sync(0xFFFFFFFFu, i2, o);
            if (om1 > m1) {
                bool keep = (m1 >= om2);
                m2 = keep ? m1 : om2;
                i2 = keep ? i1 : oi2;
                m1 = om1; i1 = oi1;
            } else if (om1 > m2) {
                m2 = om1; i2 = oi1;
            }
        }

        if (q == 0) {
            float ri  = g_r[row];
            float t   = __fdividef(ri, fmaf(ri, A, EPSF));
            float w1  = m1 * t, w2 = m2 * t;
            float inv = __fdividef(1.0f, w1 + w2 + EPSF);
            reinterpret_cast<float2*>(out)[row] = make_float2(i1, i2);
            reinterpret_cast<float2*>(out)[(size_t)S + row] =
                make_float2(w1 * inv, w2 * inv);
        }
    }
}

// ---------------------------------------------------------------------------
// Generic fallback (k != 2): warp-per-row (known-correct R3 code)
// ---------------------------------------------------------------------------
__global__ void k_final_gen(const float* __restrict__ logits,
                            float* __restrict__ out, int S, int k, size_t out_n) {
    int lane = threadIdx.x & 31;
    int warp = (blockIdx.x * blockDim.x + threadIdx.x) >> 5;
    int nw   = (gridDim.x * blockDim.x) >> 5;
    float2 cc = ((const float2*)g_c)[lane];

    for (int row = warp; row < S; row += nw) {
        float2 x = ((const float2*)logits)[(size_t)row * 32 + lane];
        float m = fmaxf(x.x, x.y);
        #pragma unroll
        for (int o = 16; o; o >>= 1) m = fmaxf(m, __shfl_xor_sync(0xFFFFFFFFu, m, o));
        float u0 = __expf(x.x - m) * cc.x;
        float u1 = __expf(x.y - m) * cc.y;
        float A = u0 + u1;
        #pragma unroll
        for (int o = 16; o; o >>= 1) A += __shfl_xor_sync(0xFFFFFFFFu, A, o);
        float ri = g_r[row];
        float denom = ri * A + EPSF;
        float lu0 = u0, lu1 = u1;
        float vals[8]; int idxs[8];
        for (int t = 0; t < k; t++) {
            float lv; int li;
            if (lu0 >= lu1) { lv = lu0; li = 2 * lane; }
            else            { lv = lu1; li = 2 * lane + 1; }
            #pragma unroll
            for (int o = 16; o; o >>= 1) {
                float ov = __shfl_xor_sync(0xFFFFFFFFu, lv, o);
                int   oi = __shfl_xor_sync(0xFFFFFFFFu, li, o);
                if (ov > lv || (ov == lv && oi < li)) { lv = ov; li = oi; }
            }
            vals[t] = lv; idxs[t] = li;
            if (li == 2 * lane)     lu0 = -1.f;
            if (li == 2 * lane + 1) lu1 = -1.f;
        }
        if (lane == 0) {
            float v[8], vs = 0.f;
            for (int t = 0; t < k; t++) { v[t] = ri * vals[t] / denom; vs += v[t]; }
            float inv = 1.0f / (vs + EPSF);
            for (int t = 0; t < k; t++) {
                size_t pi = (size_t)row * k + t;
                size_t pw = (size_t)S * k + pi;
                if (pi < out_n) out[pi] = (float)idxs[t];
                if (pw < out_n) out[pw] = v[t] * inv;
            }
        }
    }
}

// ---------------------------------------------------------------------------
extern "C" void kernel_launch(void* const* d_in, const int* in_sizes, int n_in,
                              void* d_out, int out_size) {
    const float* logits = (const float*)d_in[0];
    float*       out    = (float*)d_out;

    int S = in_sizes[0] / EXPERTS;
    if (S > S_MAX) S = S_MAX;
    if (S < 1) S = 1;
    float col_target = (float)S / (float)EXPERTS;

    int k = (int)((size_t)out_size / (2 * (size_t)S));
    if (k < 1) k = 1;
    if (k > 8) k = 8;

    k_prep<<<NB, NT>>>(logits, S, col_target);          // includes iteration 1
    for (int it = 1; it < 10; it++)
        k_iter<<<NB, NT>>>(S, col_target);              // iterations 2..10
    if (k == 2)
        k_final2<<<NB, NT>>>(logits, out, S);
    else
        k_final_gen<<<4096, 256>>>(logits, out, S, k, (size_t)out_size);
}